// round 5
// baseline (speedup 1.0000x reference)
#include <cuda_runtime.h>
#include <cstdint>

#define CIN     32
#define COUT    32
#define KVOL    27
#define ROWS_W  16
#define THREADS 256
#define WARPS   8
#define W_TAP   4096
#define WBYTES  (KVOL * W_TAP)          // 110592
#define CAP     1000000

// K-permuted, tf32-rounded feature table (128 MB device scratch)
__device__ __align__(16) uint32_t g_featp[(size_t)CAP * 32];
__device__ int g_valid_is_u8;

__global__ void detect_valid_dtype(const unsigned char* __restrict__ v, int nbytes) {
    int nz = 0;
    for (int i = threadIdx.x; i < nbytes; i += 32)
        if ((i & 3) && v[i]) nz = 1;
    nz = __any_sync(0xffffffffu, nz);
    if (threadIdx.x == 0) g_valid_is_u8 = nz;
}

__device__ __forceinline__ uint32_t f2tf32(float f) {
    uint32_t t;
    asm("cvt.rna.tf32.f32 %0, %1;" : "=r"(t) : "f"(f));
    return t;
}
__device__ __forceinline__ void mma_tf32(float& d0, float& d1, float& d2, float& d3,
                                         uint32_t a0, uint32_t a1, uint32_t a2, uint32_t a3,
                                         uint32_t b0, uint32_t b1) {
    asm volatile(
        "mma.sync.aligned.m16n8k8.row.col.f32.tf32.tf32.f32 "
        "{%0,%1,%2,%3}, {%4,%5,%6,%7}, {%8,%9}, {%0,%1,%2,%3};"
        : "+f"(d0), "+f"(d1), "+f"(d2), "+f"(d3)
        : "r"(a0), "r"(a1), "r"(a2), "r"(a3), "r"(b0), "r"(b1));
}

// prepass: g_featp[n][p] = tf32(feat[n][k(p)]),  k = 8*ks + 4*h + tig,  p = 8*tig + 2*ks + h
__global__ void prepass(const float* __restrict__ feat, int N) {
    int stride = gridDim.x * blockDim.x;
    int total = N * 32;
    for (int i = blockIdx.x * blockDim.x + threadIdx.x; i < total; i += stride) {
        int p = i & 31;
        int tig = p >> 3, r = p & 7, ks = r >> 1, h = r & 1;
        int k = 8 * ks + 4 * h + tig;
        g_featp[i] = f2tf32(feat[(i & ~31) + k]);
    }
}

// ---------------- main kernel ----------------
__global__ void __launch_bounds__(THREADS, 2)
spconv_mma(const float* __restrict__ weight,
           const float* __restrict__ bias,
           const int* __restrict__ kidx,
           const unsigned char* __restrict__ kvalid,
           float* __restrict__ out,
           int N)
{
    extern __shared__ __align__(16) char smem[];

    const int tid  = threadIdx.x;
    const int w    = tid >> 5;
    const int lane = tid & 31;
    const int gid  = lane >> 2;
    const int tig  = lane & 3;
    const bool u8  = (g_valid_is_u8 != 0);
    const int* kvalid32 = (const int*)kvalid;

    // pack weights: identical fragment layout to R3/R4 (validated)
    for (int i = tid; i < KVOL * 1024; i += THREADS) {
        int tap = i >> 10, d = i & 1023;
        int p = d >> 7, ln = (d >> 2) & 31, q = d & 3;
        int f = 2 * p + (q >> 1);
        int ks = f >> 2, nt = f & 3;
        int tg = ln & 3, gd = ln >> 2;
        int c = ks * 8 + tg + ((q & 1) ? 4 : 0);
        int j = nt * 8 + gd;
        ((uint32_t*)smem)[(size_t)tap * 1024 + d] = f2tf32(weight[(size_t)tap * 1024 + c * 32 + j]);
    }
    __syncthreads();

    float2 bb[4];
    #pragma unroll
    for (int nt = 0; nt < 4; nt++) {
        bb[nt].x = bias[nt * 8 + tig * 2 + 0];
        bb[nt].y = bias[nt * 8 + tig * 2 + 1];
    }

    const int ntiles = (N + ROWS_W - 1) / ROWS_W;
    const int TW     = gridDim.x * WARPS;
    const int gw     = blockIdx.x * WARPS + w;

    int myT = 0;
    for (int t = gw; t < ntiles; t += TW) myT++;
    const int total = myT * KVOL;
    if (total == 0) return;

    // idx-load cursor
    int lS = gw, lTap = 0;
    int i0, i1, v0, v1;                       // prefetched idx/valid for next issue
    auto loadI = [&]() {
        int g0 = lS * ROWS_W + gid, g1 = g0 + 8;
        size_t o = (size_t)lTap * N;
        i0 = 0; i1 = 0; v0 = 0; v1 = 0;
        if (g0 < N) {
            i0 = kidx[o + g0];
            v0 = u8 ? (int)kvalid[o + g0] : (kvalid32[o + g0] != 0);
        }
        if (g1 < N) {
            i1 = kidx[o + g1];
            v1 = u8 ? (int)kvalid[o + g1] : (kvalid32[o + g1] != 0);
        }
        if (++lTap == KVOL) { lTap = 0; lS += TW; }
    };

    const uint4 z4 = make_uint4(0, 0, 0, 0);
    auto issueA = [&](uint4& x0, uint4& x1, uint4& y0, uint4& y1) {
        if (v0) {
            const uint4* p0 = (const uint4*)(g_featp + (size_t)(uint32_t)i0 * 32 + tig * 8);
            x0 = p0[0]; x1 = p0[1];
        } else { x0 = z4; x1 = z4; }
        if (v1) {
            const uint4* p1 = (const uint4*)(g_featp + (size_t)(uint32_t)i1 * 32 + tig * 8);
            y0 = p1[0]; y1 = p1[1];
        } else { y0 = z4; y1 = z4; }
    };

    // compute cursor
    int ctap = 0, cS = gw;
    float acc[4][4];
    #pragma unroll
    for (int nt = 0; nt < 4; nt++)
        #pragma unroll
        for (int r = 0; r < 4; r++) acc[nt][r] = 0.0f;

    // double-buffered A fragments
    uint4 Ax0, Ax1, Ay0, Ay1;   // buffer 0
    uint4 Bx0, Bx1, By0, By1;   // buffer 1

    // prologue: idx(job0) -> issue A(job0) -> buf0 ; idx(job1) prefetched
    loadI();
    issueA(Ax0, Ax1, Ay0, Ay1);
    if (total > 1) loadI();

    auto body = [&](int j, uint4& cx0, uint4& cx1, uint4& cy0, uint4& cy1,
                           uint4& nx0, uint4& nx1, uint4& ny0, uint4& ny1) {
        // issue A for j+1 (idx already in i0/i1/v0/v1)
        if (j + 1 < total) issueA(nx0, nx1, ny0, ny1);
        // prefetch idx for j+2
        if (j + 2 < total) loadI();

        // B fragments for this tap
        const float4* wp = (const float4*)(smem + (size_t)ctap * W_TAP);
        float4 bf[8];
        #pragma unroll
        for (int p = 0; p < 8; p++) bf[p] = wp[p * 32 + lane];

        // 16 HMMA: ks 0..3 from (cx0,cx1)/(cy0,cy1) fields
        #pragma unroll
        for (int ks = 0; ks < 4; ks++) {
            uint32_t a0, a1, a2, a3;
            if (ks == 0)      { a0 = cx0.x; a2 = cx0.y; a1 = cy0.x; a3 = cy0.y; }
            else if (ks == 1) { a0 = cx0.z; a2 = cx0.w; a1 = cy0.z; a3 = cy0.w; }
            else if (ks == 2) { a0 = cx1.x; a2 = cx1.y; a1 = cy1.x; a3 = cy1.y; }
            else              { a0 = cx1.z; a2 = cx1.w; a1 = cy1.z; a3 = cy1.w; }
            #pragma unroll
            for (int nt = 0; nt < 4; nt++) {
                float4 v = bf[ks * 2 + (nt >> 1)];
                uint32_t b0 = (nt & 1) ? __float_as_uint(v.z) : __float_as_uint(v.x);
                uint32_t b1 = (nt & 1) ? __float_as_uint(v.w) : __float_as_uint(v.y);
                mma_tf32(acc[nt][0], acc[nt][1], acc[nt][2], acc[nt][3],
                         a0, a1, a2, a3, b0, b1);
            }
        }

        // tile boundary: epilogue
        if (++ctap == KVOL) {
            int gr = cS * ROWS_W + gid;
            #pragma unroll
            for (int nt = 0; nt < 4; nt++) {
                int col = nt * 8 + tig * 2;
                if (gr < N) {
                    float2 o = { acc[nt][0] + bb[nt].x, acc[nt][1] + bb[nt].y };
                    *(float2*)(out + (size_t)gr * COUT + col) = o;
                }
                if (gr + 8 < N) {
                    float2 o = { acc[nt][2] + bb[nt].x, acc[nt][3] + bb[nt].y };
                    *(float2*)(out + (size_t)(gr + 8) * COUT + col) = o;
                }
                acc[nt][0] = acc[nt][1] = acc[nt][2] = acc[nt][3] = 0.0f;
            }
            ctap = 0;
            cS += TW;
        }
    };

    int j = 0;
    for (; j + 2 <= total; j += 2) {
        body(j,     Ax0, Ax1, Ay0, Ay1, Bx0, Bx1, By0, By1);
        body(j + 1, Bx0, Bx1, By0, By1, Ax0, Ax1, Ay0, Ay1);
    }
    if (j < total)
        body(j, Ax0, Ax1, Ay0, Ay1, Bx0, Bx1, By0, By1);
}

extern "C" void kernel_launch(void* const* d_in, const int* in_sizes, int n_in,
                              void* d_out, int out_size) {
    const float*         feat   = (const float*)d_in[0];          // [N, 32]
    const float*         weight = (const float*)d_in[1];          // [27, 32, 32]
    const float*         bias   = (const float*)d_in[2];          // [32]
    const int*           kidx   = (const int*)d_in[3];            // [27, N]
    const unsigned char* kvalid = (const unsigned char*)d_in[4];  // [27, N] bool
    float* out = (float*)d_out;

    const int N = in_sizes[0] / CIN;

    int sms = 148;
    cudaDeviceGetAttribute(&sms, cudaDevAttrMultiProcessorCount, 0);

    cudaFuncSetAttribute(spconv_mma, cudaFuncAttributeMaxDynamicSharedMemorySize, WBYTES);

    detect_valid_dtype<<<1, 32>>>(kvalid, 16384);
    prepass<<<sms * 8, 256>>>(feat, N);
    spconv_mma<<<sms * 2, THREADS, WBYTES>>>(weight, bias, kidx, kvalid, out, N);
}

// round 6
// speedup vs baseline: 1.2985x; 1.2985x over previous
#include <cuda_runtime.h>
#include <cstdint>

#define CIN     32
#define COUT    32
#define KVOL    27
#define WARPS   16
#define THREADS 512
#define NSTAGE  3
#define ROWS_W  16
#define SLICE   2048
#define W_TAP   4096
#define WBYTES  (KVOL * W_TAP)          // 110592
#define SMEM_TOTAL (WBYTES + WARPS * NSTAGE * SLICE)   // 208896
#define CAP     1000000

// K-permuted, tf32-pre-rounded feature table (device scratch)
__device__ __align__(16) uint32_t g_featp[(size_t)CAP * 32];
__device__ int g_valid_is_u8;

__global__ void detect_valid_dtype(const unsigned char* __restrict__ v, int nbytes) {
    int nz = 0;
    for (int i = threadIdx.x; i < nbytes; i += blockDim.x)
        if ((i & 3) && v[i]) nz = 1;
    if (__syncthreads_or(nz) && threadIdx.x == 0) g_valid_is_u8 = 1;
}

__device__ __forceinline__ uint32_t smem_u32(const void* p) {
    uint32_t a;
    asm("{ .reg .u64 t; cvta.to.shared.u64 t, %1; cvt.u32.u64 %0, t; }" : "=r"(a) : "l"(p));
    return a;
}
__device__ __forceinline__ void cp16(uint32_t dst, const void* src, uint32_t nbytes) {
    asm volatile("cp.async.cg.shared.global [%0], [%1], 16, %2;"
                 :: "r"(dst), "l"(src), "r"(nbytes) : "memory");
}
#define CP_COMMIT() asm volatile("cp.async.commit_group;" ::: "memory")
#define CP_WAIT1()  asm volatile("cp.async.wait_group 1;" ::: "memory")

__device__ __forceinline__ uint32_t f2tf32(float f) {
    uint32_t t;
    asm("cvt.rna.tf32.f32 %0, %1;" : "=r"(t) : "f"(f));
    return t;
}
__device__ __forceinline__ void mma_tf32(float& d0, float& d1, float& d2, float& d3,
                                         uint32_t a0, uint32_t a1, uint32_t a2, uint32_t a3,
                                         uint32_t b0, uint32_t b1) {
    asm volatile(
        "mma.sync.aligned.m16n8k8.row.col.f32.tf32.tf32.f32 "
        "{%0,%1,%2,%3}, {%4,%5,%6,%7}, {%8,%9}, {%0,%1,%2,%3};"
        : "+f"(d0), "+f"(d1), "+f"(d2), "+f"(d3)
        : "r"(a0), "r"(a1), "r"(a2), "r"(a3), "r"(b0), "r"(b1));
}

// prepass: g_featp[n][p] = tf32(feat[n][k]), p = 8*tig + 2*ks + h, k = 8*ks + 4*h + tig
// Output uint4 j per row (j=0..7): tig=j>>1, kbase=tig+(j&1)*16, k = kbase+4*m
__global__ void prepass(const float* __restrict__ feat, int N) {
    int stride = gridDim.x * blockDim.x;
    int total = N * 8;
    for (int i = blockIdx.x * blockDim.x + threadIdx.x; i < total; i += stride) {
        int n = i >> 3, j = i & 7;
        int tig = j >> 1, kbase = tig + ((j & 1) << 4);
        const float* src = feat + (size_t)n * 32 + kbase;
        uint4 o;
        o.x = f2tf32(src[0]);
        o.y = f2tf32(src[4]);
        o.z = f2tf32(src[8]);
        o.w = f2tf32(src[12]);
        ((uint4*)g_featp)[i] = o;
    }
}

struct Pref { int idx[4]; unsigned val; };

// ---------------- main kernel ----------------
__global__ void __launch_bounds__(THREADS, 1)
spconv_mma(const float* __restrict__ weight,
           const float* __restrict__ bias,
           const int* __restrict__ kidx,
           const unsigned char* __restrict__ kvalid,
           float* __restrict__ out,
           int N)
{
    extern __shared__ __align__(16) char smem[];
    const uint32_t sb = smem_u32(smem);

    const int tid  = threadIdx.x;
    const int w    = tid >> 5;
    const int lane = tid & 31;
    const int gid  = lane >> 2;
    const int tig  = lane & 3;
    const int r4   = lane >> 3;
    const int ch   = lane & 7;
    const bool u8  = (g_valid_is_u8 != 0);
    const int* kvalid32 = (const int*)kvalid;

    // pack weights (validated fragment layout)
    for (int i = tid; i < KVOL * 1024; i += THREADS) {
        int tap = i >> 10, d = i & 1023;
        int p = d >> 7, ln = (d >> 2) & 31, q = d & 3;
        int f = 2 * p + (q >> 1);
        int ks = f >> 2, nt = f & 3;
        int tg = ln & 3, gd = ln >> 2;
        int c = ks * 8 + tg + ((q & 1) ? 4 : 0);
        int j = nt * 8 + gd;
        ((uint32_t*)smem)[(size_t)tap * 1024 + d] = f2tf32(weight[(size_t)tap * 1024 + c * 32 + j]);
    }
    __syncthreads();

    float2 bb[4];
    #pragma unroll
    for (int nt = 0; nt < 4; nt++) {
        bb[nt].x = bias[nt * 8 + tig * 2 + 0];
        bb[nt].y = bias[nt * 8 + tig * 2 + 1];
    }

    const int ntiles = (N + ROWS_W - 1) / ROWS_W;
    const int TW     = gridDim.x * WARPS;
    const int gw     = blockIdx.x * WARPS + w;

    int myT = 0;
    for (int t = gw; t < ntiles; t += TW) myT++;
    const int total = myT * KVOL;
    if (total == 0) return;

    const uint32_t aBase = sb + WBYTES + (uint32_t)(w * NSTAGE) * SLICE;
    const char*    fbase = (const char*)g_featp;

    uint32_t dsto[4];
    #pragma unroll
    for (int q = 0; q < 4; q++) {
        int r = r4 + 4 * q;
        dsto[q] = (uint32_t)r * 128 + (uint32_t)((ch ^ (r & 7)) << 4);
    }

    auto load_idx = [&](int S, int tap, Pref& P) {
        int base = S * ROWS_W + r4;
        unsigned vm = 0;
        #pragma unroll
        for (int q = 0; q < 4; q++) {
            int g = base + 4 * q;
            int id = 0; bool va = false;
            if (S < ntiles && g < N) {
                size_t o = (size_t)tap * N + g;
                id = kidx[o];
                va = u8 ? (kvalid[o] != 0) : (kvalid32[o] != 0);
            }
            P.idx[q] = id;
            vm |= va ? (1u << q) : 0u;
        }
        P.val = vm;
    };
    auto issue = [&](const Pref& P, int stage) {
        uint32_t ab = aBase + (uint32_t)stage * SLICE;
        #pragma unroll
        for (int q = 0; q < 4; q++) {
            const char* src = fbase + ((size_t)(uint32_t)P.idx[q] << 7) + (ch << 4);
            cp16(ab + dsto[q], src, ((P.val >> q) & 1u) ? 16u : 0u);
        }
    };

    Pref Pa;
    load_idx(gw, 0, Pa);
    issue(Pa, 0); CP_COMMIT();
    if (total > 1) { load_idx(gw, 1, Pa); issue(Pa, 1); }
    CP_COMMIT();
    if (total > 2) load_idx(gw, 2, Pa);

    int ptap = 3, pS = gw;
    if (ptap >= KVOL) { ptap -= KVOL; pS += TW; }
    int ctap = 0, cS = gw;

    float acc[4][4];
    #pragma unroll
    for (int nt = 0; nt < 4; nt++)
        #pragma unroll
        for (int r = 0; r < 4; r++) acc[nt][r] = 0.0f;

    // precomputed A LDS offsets (swizzled chunk positions)
    const uint32_t cA0 = (uint32_t)(((2 * tig)     ^ gid) << 4);
    const uint32_t cA1 = (uint32_t)(((2 * tig + 1) ^ gid) << 4);

    for (int jl = 0; jl < total; jl++) {
        CP_WAIT1();
        __syncwarp();

        if (jl + 2 < total) issue(Pa, (jl + 2) % NSTAGE);
        CP_COMMIT();

        if (jl + 3 < total) {
            load_idx(pS, ptap, Pa);
            if (++ptap == KVOL) { ptap = 0; pS += TW; }
        }

        const char* Ab = (const char*)smem + WBYTES
                       + (size_t)(w * NSTAGE + jl % NSTAGE) * SLICE;

        // A fragments: 4x LDS.128, conflict-free, pre-rounded tf32
        const char* pA = Ab + (size_t)gid * 128;
        const char* pB = Ab + (size_t)(gid + 8) * 128;
        uint4 L0 = *(const uint4*)(pA + cA0);
        uint4 L1 = *(const uint4*)(pA + cA1);
        uint4 M0 = *(const uint4*)(pB + cA0);
        uint4 M1 = *(const uint4*)(pB + cA1);

        const float4* wp = (const float4*)(smem + (size_t)ctap * W_TAP);

        #pragma unroll
        for (int ks = 0; ks < 4; ks++) {
            float4 bf0 = wp[(ks * 2 + 0) * 32 + lane];
            float4 bf1 = wp[(ks * 2 + 1) * 32 + lane];
            uint32_t a0, a1, a2, a3;
            if (ks == 0)      { a0 = L0.x; a2 = L0.y; a1 = M0.x; a3 = M0.y; }
            else if (ks == 1) { a0 = L0.z; a2 = L0.w; a1 = M0.z; a3 = M0.w; }
            else if (ks == 2) { a0 = L1.x; a2 = L1.y; a1 = M1.x; a3 = M1.y; }
            else              { a0 = L1.z; a2 = L1.w; a1 = M1.z; a3 = M1.w; }
            #pragma unroll
            for (int nt = 0; nt < 4; nt++) {
                float4 v = (nt >> 1) ? bf1 : bf0;
                uint32_t b0 = (nt & 1) ? __float_as_uint(v.z) : __float_as_uint(v.x);
                uint32_t b1 = (nt & 1) ? __float_as_uint(v.w) : __float_as_uint(v.y);
                mma_tf32(acc[nt][0], acc[nt][1], acc[nt][2], acc[nt][3],
                         a0, a1, a2, a3, b0, b1);
            }
        }

        if (++ctap == KVOL) {
            int gr = cS * ROWS_W + gid;
            #pragma unroll
            for (int nt = 0; nt < 4; nt++) {
                int col = nt * 8 + tig * 2;
                if (gr < N) {
                    float2 o = { acc[nt][0] + bb[nt].x, acc[nt][1] + bb[nt].y };
                    *(float2*)(out + (size_t)gr * COUT + col) = o;
                }
                if (gr + 8 < N) {
                    float2 o = { acc[nt][2] + bb[nt].x, acc[nt][3] + bb[nt].y };
                    *(float2*)(out + (size_t)(gr + 8) * COUT + col) = o;
                }
                acc[nt][0] = acc[nt][1] = acc[nt][2] = acc[nt][3] = 0.0f;
            }
            ctap = 0;
            cS += TW;
        }
    }
}

extern "C" void kernel_launch(void* const* d_in, const int* in_sizes, int n_in,
                              void* d_out, int out_size) {
    const float*         feat   = (const float*)d_in[0];          // [N, 32]
    const float*         weight = (const float*)d_in[1];          // [27, 32, 32]
    const float*         bias   = (const float*)d_in[2];          // [32]
    const int*           kidx   = (const int*)d_in[3];            // [27, N]
    const unsigned char* kvalid = (const unsigned char*)d_in[4];  // [27, N] bool
    float* out = (float*)d_out;

    const int N = in_sizes[0] / CIN;

    int sms = 148;
    cudaDeviceGetAttribute(&sms, cudaDevAttrMultiProcessorCount, 0);

    cudaFuncSetAttribute(spconv_mma, cudaFuncAttributeMaxDynamicSharedMemorySize, SMEM_TOTAL);

    detect_valid_dtype<<<1, 256>>>(kvalid, 2048);
    prepass<<<sms * 8, 256>>>(feat, N);
    spconv_mma<<<sms, THREADS, SMEM_TOTAL>>>(weight, bias, kidx, kvalid, out, N);
}

// round 7
// speedup vs baseline: 1.3822x; 1.0644x over previous
#include <cuda_runtime.h>
#include <cuda_fp16.h>
#include <cstdint>

#define CIN     32
#define COUT    32
#define KVOL    27
#define WARPS   16
#define THREADS 512
#define NSTAGE  4
#define ROWS_W  16
#define SLICE   1024                    // 16 rows * 64 B
#define W_TAP   2048
#define WBYTES  (KVOL * W_TAP)          // 55296
#define SMEM_TOTAL (WBYTES + WARPS * NSTAGE * SLICE)   // 120832
#define CAP     1000000

// K-permuted fp16 feature table (64 MB device scratch)
__device__ __align__(16) __half g_feath[(size_t)CAP * 32];
__device__ int g_valid_is_u8;

__global__ void detect_valid_dtype(const unsigned char* __restrict__ v, int nbytes) {
    int nz = 0;
    for (int i = threadIdx.x; i < nbytes; i += blockDim.x)
        if ((i & 3) && v[i]) nz = 1;
    if (__syncthreads_or(nz) && threadIdx.x == 0) g_valid_is_u8 = 1;
}

__device__ __forceinline__ uint32_t smem_u32(const void* p) {
    uint32_t a;
    asm("{ .reg .u64 t; cvta.to.shared.u64 t, %1; cvt.u32.u64 %0, t; }" : "=r"(a) : "l"(p));
    return a;
}
__device__ __forceinline__ void cp16(uint32_t dst, const void* src, uint32_t nbytes) {
    asm volatile("cp.async.cg.shared.global [%0], [%1], 16, %2;"
                 :: "r"(dst), "l"(src), "r"(nbytes) : "memory");
}
#define CP_COMMIT() asm volatile("cp.async.commit_group;" ::: "memory")
#define CP_WAIT2()  asm volatile("cp.async.wait_group 2;" ::: "memory")

__device__ __forceinline__ uint32_t h2pack(float a, float b) {
    __half2 h = __floats2half2_rn(a, b);
    return *(uint32_t*)&h;
}
__device__ __forceinline__ void mma_f16(float& d0, float& d1, float& d2, float& d3,
                                        uint32_t a0, uint32_t a1, uint32_t a2, uint32_t a3,
                                        uint32_t b0, uint32_t b1) {
    asm volatile(
        "mma.sync.aligned.m16n8k16.row.col.f32.f16.f16.f32 "
        "{%0,%1,%2,%3}, {%4,%5,%6,%7}, {%8,%9}, {%0,%1,%2,%3};"
        : "+f"(d0), "+f"(d1), "+f"(d2), "+f"(d3)
        : "r"(a0), "r"(a1), "r"(a2), "r"(a3), "r"(b0), "r"(b1));
}

// prepass: per (n, tig, kc) write 4 halves:
// featp[n][tig*8 + kc*4 + j] = fp16(feat[n][kc*16 + (j<2 ? 2*tig+j : 2*tig+8+(j-2))])
__global__ void prepass(const float* __restrict__ feat, int N) {
    int stride = gridDim.x * blockDim.x;
    int total = N * 8;
    for (int i = blockIdx.x * blockDim.x + threadIdx.x; i < total; i += stride) {
        int n = i >> 3, s = i & 7;
        int tig = s >> 1, kc = s & 1;
        const float* src = feat + (size_t)n * 32 + kc * 16 + 2 * tig;
        uint2 o;
        o.x = h2pack(src[0], src[1]);   // k=2tig, 2tig+1
        o.y = h2pack(src[8], src[9]);   // k=2tig+8, 2tig+9
        ((uint2*)g_feath)[(size_t)n * 8 + tig * 2 + kc] = o;
    }
}

struct Pref { int idx0, idx1; int v0, v1; };

// ---------------- main kernel ----------------
__global__ void __launch_bounds__(THREADS, 1)
spconv_mma(const float* __restrict__ weight,
           const float* __restrict__ bias,
           const int* __restrict__ kidx,
           const unsigned char* __restrict__ kvalid,
           float* __restrict__ out,
           int N)
{
    extern __shared__ __align__(16) char smem[];
    const uint32_t sb = smem_u32(smem);

    const int tid  = threadIdx.x;
    const int w    = tid >> 5;
    const int lane = tid & 31;
    const int gid  = lane >> 2;
    const int tig  = lane & 3;
    const int r8   = lane >> 2;   // gather row base (0..7), chunk = lane&3
    const int ch   = lane & 3;
    const bool u8  = (g_valid_is_u8 != 0);
    const int* kvalid32 = (const int*)kvalid;

    // ---- pack fp16 B fragments: per tap 4 uint4-rows of 32 lanes ----
    // uint4 entry [p][lane]: kc=p>>1, npair=p&1; q-th u32: nt=npair*2+(q>>1), bsel=q&1
    // value = half2( W[k][nt*8+gd], W[k+1][nt*8+gd] ), k = kc*16 + 2*tg + (bsel?8:0)
    for (int i = tid; i < KVOL * 512; i += THREADS) {
        int tap = i >> 9, d = i & 511;
        int p = d >> 7, ln = (d >> 2) & 31, q = d & 3;
        int kc = p >> 1;
        int nt = (p & 1) * 2 + (q >> 1);
        int tg = ln & 3, gd = ln >> 2;
        int k = kc * 16 + 2 * tg + ((q & 1) ? 8 : 0);
        const float* wrow = weight + (size_t)tap * 1024;
        ((uint32_t*)smem)[(size_t)tap * 512 + d] =
            h2pack(wrow[k * 32 + nt * 8 + gd], wrow[(k + 1) * 32 + nt * 8 + gd]);
    }
    __syncthreads();

    float2 bb[4];
    #pragma unroll
    for (int nt = 0; nt < 4; nt++) {
        bb[nt].x = bias[nt * 8 + tig * 2 + 0];
        bb[nt].y = bias[nt * 8 + tig * 2 + 1];
    }

    const int ntiles = (N + ROWS_W - 1) / ROWS_W;
    const int TW     = gridDim.x * WARPS;
    const int gw     = blockIdx.x * WARPS + w;

    int myT = 0;
    for (int t = gw; t < ntiles; t += TW) myT++;
    const int total = myT * KVOL;
    if (total == 0) return;

    const uint32_t aBase = sb + WBYTES + (uint32_t)(w * NSTAGE) * SLICE;
    const char*    fbase = (const char*)g_feath;

    // lane owns rows r8 and r8+8, chunk ch (16B): dst contiguous, no swizzle
    const uint32_t dst0 = (uint32_t)r8 * 64 + (uint32_t)ch * 16;
    const uint32_t dst1 = dst0 + 512;

    auto load_idx = [&](int S, int tap, Pref& P) {
        P.idx0 = 0; P.idx1 = 0; P.v0 = 0; P.v1 = 0;
        int g0 = S * ROWS_W + r8, g1 = g0 + 8;
        if (S < ntiles) {
            size_t o = (size_t)tap * N;
            if (g0 < N) {
                P.idx0 = kidx[o + g0];
                P.v0 = u8 ? (int)kvalid[o + g0] : (kvalid32[o + g0] != 0);
            }
            if (g1 < N) {
                P.idx1 = kidx[o + g1];
                P.v1 = u8 ? (int)kvalid[o + g1] : (kvalid32[o + g1] != 0);
            }
        }
    };
    auto issue = [&](const Pref& P, int stage) {
        uint32_t ab = aBase + (uint32_t)stage * SLICE;
        cp16(ab + dst0, fbase + ((size_t)(uint32_t)P.idx0 << 6) + (ch << 4), P.v0 ? 16u : 0u);
        cp16(ab + dst1, fbase + ((size_t)(uint32_t)P.idx1 << 6) + (ch << 4), P.v1 ? 16u : 0u);
    };

    // ---- prologue: jobs 0..2 issued, idx(job3) prefetched ----
    Pref Pa;
    load_idx(gw, 0, Pa);
    issue(Pa, 0); CP_COMMIT();
    if (total > 1) { load_idx(gw, 1, Pa); issue(Pa, 1); }
    CP_COMMIT();
    if (total > 2) { load_idx(gw, 2, Pa); issue(Pa, 2); }
    CP_COMMIT();
    if (total > 3) load_idx(gw, 3, Pa);

    int ptap = 4, pS = gw;
    while (ptap >= KVOL) { ptap -= KVOL; pS += TW; }
    int ctap = 0, cS = gw;

    float acc[4][4];
    #pragma unroll
    for (int nt = 0; nt < 4; nt++)
        #pragma unroll
        for (int r = 0; r < 4; r++) acc[nt][r] = 0.0f;

    for (int jl = 0; jl < total; jl++) {
        CP_WAIT2();
        __syncwarp();

        if (jl + 3 < total) issue(Pa, (jl + 3) & (NSTAGE - 1));
        CP_COMMIT();

        if (jl + 4 < total) {
            load_idx(pS, ptap, Pa);
            if (++ptap == KVOL) { ptap = 0; pS += TW; }
        }

        const char* Ab = (const char*)smem + WBYTES
                       + (size_t)(w * NSTAGE + (jl & (NSTAGE - 1))) * SLICE;

        // A fragments: 2x LDS.128, contiguous, conflict-free
        uint4 L = *(const uint4*)(Ab + (size_t)gid * 64 + tig * 16);
        uint4 M = *(const uint4*)(Ab + (size_t)(gid + 8) * 64 + tig * 16);

        const uint4* wp = (const uint4*)(smem + (size_t)ctap * W_TAP);

        #pragma unroll
        for (int kc = 0; kc < 2; kc++) {
            uint4 bf0 = wp[(kc * 2 + 0) * 32 + lane];   // nt 0,1
            uint4 bf1 = wp[(kc * 2 + 1) * 32 + lane];   // nt 2,3
            uint32_t a0 = kc ? L.z : L.x;
            uint32_t a2 = kc ? L.w : L.y;
            uint32_t a1 = kc ? M.z : M.x;
            uint32_t a3 = kc ? M.w : M.y;
            mma_f16(acc[0][0], acc[0][1], acc[0][2], acc[0][3], a0, a1, a2, a3, bf0.x, bf0.y);
            mma_f16(acc[1][0], acc[1][1], acc[1][2], acc[1][3], a0, a1, a2, a3, bf0.z, bf0.w);
            mma_f16(acc[2][0], acc[2][1], acc[2][2], acc[2][3], a0, a1, a2, a3, bf1.x, bf1.y);
            mma_f16(acc[3][0], acc[3][1], acc[3][2], acc[3][3], a0, a1, a2, a3, bf1.z, bf1.w);
        }

        if (++ctap == KVOL) {
            int gr = cS * ROWS_W + gid;
            #pragma unroll
            for (int nt = 0; nt < 4; nt++) {
                int col = nt * 8 + tig * 2;
                if (gr < N) {
                    float2 o = { acc[nt][0] + bb[nt].x, acc[nt][1] + bb[nt].y };
                    *(float2*)(out + (size_t)gr * COUT + col) = o;
                }
                if (gr + 8 < N) {
                    float2 o = { acc[nt][2] + bb[nt].x, acc[nt][3] + bb[nt].y };
                    *(float2*)(out + (size_t)(gr + 8) * COUT + col) = o;
                }
                acc[nt][0] = acc[nt][1] = acc[nt][2] = acc[nt][3] = 0.0f;
            }
            ctap = 0;
            cS += TW;
        }
    }
}

extern "C" void kernel_launch(void* const* d_in, const int* in_sizes, int n_in,
                              void* d_out, int out_size) {
    const float*         feat   = (const float*)d_in[0];          // [N, 32]
    const float*         weight = (const float*)d_in[1];          // [27, 32, 32]
    const float*         bias   = (const float*)d_in[2];          // [32]
    const int*           kidx   = (const int*)d_in[3];            // [27, N]
    const unsigned char* kvalid = (const unsigned char*)d_in[4];  // [27, N] bool
    float* out = (float*)d_out;

    const int N = in_sizes[0] / CIN;

    int sms = 148;
    cudaDeviceGetAttribute(&sms, cudaDevAttrMultiProcessorCount, 0);

    cudaFuncSetAttribute(spconv_mma, cudaFuncAttributeMaxDynamicSharedMemorySize, SMEM_TOTAL);

    detect_valid_dtype<<<1, 256>>>(kvalid, 2048);
    prepass<<<sms * 8, 256>>>(feat, N);
    spconv_mma<<<sms, THREADS, SMEM_TOTAL>>>(weight, bias, kidx, kvalid, out, N);
}